// round 13
// baseline (speedup 1.0000x reference)
#include <cuda_runtime.h>
#include <string.h>

// LearnableConvCensus: depthwise 3x3 conv (multiplier 8) -> sigmoid -> mean over 8.
// B=4, C=64, H=W=256, pad=1.
//
// sigmoid(z) = 0.5 + 0.5*tanh(z/2); fold 0.5*temperature[c] into pre-scaled
// weights/bias. out = 0.5 + (sum_m tanh_m) / 16.
//
// R13: single-wave persistent strips. 512 blocks (one half-plane = 128 rows
// each) -> exactly one wave on 148 SMs x 4 CTAs. Input streams through a
// 32-row circular smem buffer via cp.async (8-row groups, 3 in flight,
// wait_group 1 + one __syncthreads per chunk), so the DRAM-latency prologue
// that cost ~33% under the 3.46-wave layout is paid once and then hidden
// under compute. Steady-state compute = R4's conv/epi double-buffer pipeline.

#define B_ 4
#define C_ 64
#define H_ 256
#define W_ 256
#define SROW 264              // smem row stride in floats (258 used, padded)
#define HALF_ROWS 128         // output rows per block
#define NCHUNKS 16            // 8-row chunks per block
#define NGROUPS 17            // 8-row cp.async load groups (130 src rows)

typedef unsigned long long ull;

__device__ __forceinline__ ull pack2(float lo, float hi) {
    ull r;
    asm("mov.b64 %0, {%1, %2};" : "=l"(r) : "f"(lo), "f"(hi));
    return r;
}
__device__ __forceinline__ ull dup2(float v) {
    ull r;
    asm("mov.b64 %0, {%1, %1};" : "=l"(r) : "f"(v));
    return r;
}
__device__ __forceinline__ void fma2(ull& acc, ull a, ull b) {
    asm("fma.rn.f32x2 %0, %1, %2, %0;" : "+l"(acc) : "l"(a), "l"(b));
}
__device__ __forceinline__ float tanh_fast(float x) {
    float y;
    asm("tanh.approx.f32 %0, %1;" : "=f"(y) : "f"(x));
    return y;
}
// s += t via FFMA-imm (multiplier = immediate 1.0f -> rt_SMSP=1)
__device__ __forceinline__ void acc1(float& s, float t) {
    asm("fma.rn.f32 %0, %1, 0f3F800000, %0;" : "+f"(s) : "f"(t));
}

__global__ __launch_bounds__(128, 4)
void census_kernel(const float* __restrict__ x, const float* __restrict__ w,
                   const float* __restrict__ bias, const float* __restrict__ temp,
                   float* __restrict__ out) {
    __shared__ float      smem[32 * SROW];   // circular buffer: src row s -> (s - h0 + 1) & 31
    __shared__ ulonglong2 wsm2[9][2];        // [k][0]=(pair0,pair1), [k][1]=(pair2,pair3)
    __shared__ ull        bsm[4];

    const int bid  = blockIdx.x;
    const int half = bid & 1;
    const int c    = (bid >> 1) & 63;
    const int b    = bid >> 7;
    const int h0   = half << 7;          // 0 or 128
    const int tid  = threadIdx.x;

    const float* xp = x + ((size_t)(b * C_ + c) * H_) * W_;

    // ---- weight prep: w layout HWIO flattened w[(kh*3+kw)*512 + c*8 + m]
    if (tid < 40) {
        const float sc = 0.5f * __ldg(&temp[c]);
        if (tid < 36) {
            const int k = tid >> 2, p = tid & 3;
            const float w0 = __ldg(&w[k * 512 + (c << 3) + 2 * p])     * sc;
            const float w1 = __ldg(&w[k * 512 + (c << 3) + 2 * p + 1]) * sc;
            ((ull*)wsm2)[k * 4 + p] = pack2(w0, w1);
        } else {
            const int p = tid - 36;
            const float b0 = __ldg(&bias[(c << 3) + 2 * p])     * sc;
            const float b1 = __ldg(&bias[(c << 3) + 2 * p + 1]) * sc;
            bsm[p] = pack2(b0, b1);
        }
    }
    // pad columns (zero conv padding at smem col idx 3 and 260), fixed forever
    if (tid < 32) {
        smem[tid * SROW + 3]   = 0.f;
        smem[tid * SROW + 260] = 0.f;
    }

    const unsigned sbase = (unsigned)__cvta_generic_to_shared(smem);

    // issue one 8-row cp.async load group g (src rows h0-1+8g .. +7); an empty
    // commit for g >= NGROUPS keeps the wait_group counting uniform.
    auto issue_group = [&](int g) {
        if (g < NGROUPS) {
            const int sg = h0 - 1 + (g << 3);
            #pragma unroll
            for (int q = 0; q < 4; q++) {
                const int slot = tid + (q << 7);      // 512 slots: 8 rows x 64 float4
                const int row  = slot >> 6;
                const int c4   = (slot & 63) << 2;
                const int src  = sg + row;
                const unsigned dst = sbase +
                    (unsigned)(((((g << 3) + row) & 31) * SROW + 4 + c4) << 2);
                const float* gp = xp + src * W_ + c4;
                const int ssz = (src >= 0 && src < H_) ? 16 : 0;  // 0 -> zero-fill
                asm volatile("cp.async.cg.shared.global [%0], [%1], 16, %2;"
                             :: "r"(dst), "l"(gp), "r"(ssz));
            }
        }
        asm volatile("cp.async.commit_group;" ::: "memory");
    };

    issue_group(0);
    issue_group(1);
    issue_group(2);

    __syncthreads();   // weights/bias/pads visible (NOT the cp.async data yet)

    const ull bp0 = bsm[0], bp1 = bsm[1], bp2 = bsm[2], bp3 = bsm[3];

    const int tx = tid & 63;   // 64 threads across width, 4 cols each
    const int ty = tid >> 6;   // 2 groups: rows [0..3] / [4..7] of each chunk
    float* outp = out + (((size_t)(b * C_ + c) * H_) + h0) * W_ + (tx << 2);

    // conv of local output row rl into acc[p][j]; smem row for src s = (rl+kh)&31
    auto conv = [&](int rl, ull acc[4][4]) {
        #pragma unroll
        for (int j = 0; j < 4; j++) {
            acc[0][j] = bp0; acc[1][j] = bp1;
            acc[2][j] = bp2; acc[3][j] = bp3;
        }
        #pragma unroll
        for (int kh = 0; kh < 3; kh++) {
            const float* rowp = &smem[((rl + kh) & 31) * SROW + (tx << 2)];
            const float  wm1 = rowp[3];
            const float4 f4  = *(const float4*)(rowp + 4);
            const float  wp4 = rowp[8];
            ull d[6];
            d[0] = dup2(wm1);
            d[1] = dup2(f4.x);
            d[2] = dup2(f4.y);
            d[3] = dup2(f4.z);
            d[4] = dup2(f4.w);
            d[5] = dup2(wp4);
            #pragma unroll
            for (int kw = 0; kw < 3; kw++) {
                const ulonglong2 w01 = wsm2[kh * 3 + kw][0];  // LDS.128 broadcast
                const ulonglong2 w23 = wsm2[kh * 3 + kw][1];
                #pragma unroll
                for (int j = 0; j < 4; j++) {
                    fma2(acc[0][j], d[j + kw], w01.x);
                    fma2(acc[1][j], d[j + kw], w01.y);
                    fma2(acc[2][j], d[j + kw], w23.x);
                    fma2(acc[3][j], d[j + kw], w23.y);
                }
            }
        }
    };

    auto epi = [&](ull acc[4][4], int rl) {
        float s[4] = {0.f, 0.f, 0.f, 0.f};
        #pragma unroll
        for (int p = 0; p < 4; p++) {
            #pragma unroll
            for (int j = 0; j < 4; j++) {
                float2 a;
                memcpy(&a, &acc[p][j], 8);
                acc1(s[j], tanh_fast(a.x));
                acc1(s[j], tanh_fast(a.y));
            }
        }
        float4 o;
        o.x = fmaf(s[0], 0.0625f, 0.5f);
        o.y = fmaf(s[1], 0.0625f, 0.5f);
        o.z = fmaf(s[2], 0.0625f, 0.5f);
        o.w = fmaf(s[3], 0.0625f, 0.5f);
        *(float4*)(outp + rl * W_) = o;
    };

    ull accA[4][4], accB[4][4];

    #pragma unroll 1
    for (int k = 0; k < NCHUNKS; k++) {
        // groups <= k+1 complete (chunk k reads buf offsets 8k..8k+9)
        asm volatile("cp.async.wait_group 1;" ::: "memory");
        __syncthreads();                 // loaded data visible; prev chunk done
        issue_group(k + 3);              // writes offsets (8k+24..8k+31)&31 — disjoint

        const int rl = (k << 3) + (ty << 2);   // this thread's 4 rows
        conv(rl, accA);
        conv(rl + 1, accB);
        epi(accA, rl);
        conv(rl + 2, accA);
        epi(accB, rl + 1);
        conv(rl + 3, accB);
        epi(accA, rl + 2);
        epi(accB, rl + 3);
    }
}

extern "C" void kernel_launch(void* const* d_in, const int* in_sizes, int n_in,
                              void* d_out, int out_size) {
    const float* x    = (const float*)d_in[0];
    const float* w    = (const float*)d_in[1];
    const float* bias = (const float*)d_in[2];
    const float* temp = (const float*)d_in[3];
    float* out = (float*)d_out;

    const int grid = B_ * C_ * 2;   // 512 blocks, one wave at 4 CTAs/SM
    census_kernel<<<grid, 128>>>(x, w, bias, temp, out);
}

// round 14
// speedup vs baseline: 1.1395x; 1.1395x over previous
#include <cuda_runtime.h>
#include <cuda_fp16.h>
#include <string.h>

// LearnableConvCensus: depthwise 3x3 conv (multiplier 8) -> sigmoid -> mean over 8.
// B=4, C=64, H=W=256, pad=1.
//
// sigmoid(z) = 0.5 + 0.5*tanh(z/2); fold 0.5*temperature[c] into pre-scaled
// weights/bias. out = 0.5 + (sum_m tanh_m) / 16.
//
// R14: fp16x2 conv. FFMA2 (64-bit operands) hits the RF-bank ceiling rt=3
// (3 even + 3 odd distinct regs); HFMA2's 32-bit operands keep rt=2 ->
// 1 cyc/FMA instead of 1.5. Tile stored as DUPLICATED half2 (same smem bytes
// as f32), multiplier pairs packed in h2; epilogue = tanh.approx.f16x2
// (2 tanh/MUFU) + hadd2 tree. Skeleton = R4 conv/epi double-buffer pipeline.

#define B_ 4
#define C_ 64
#define H_ 256
#define W_ 256
#define R_ 32                 // output rows per block
#define NROWS (R_ + 2)        // tile rows incl. halo
#define SROW 264              // smem row stride in half2 units (258 used)

typedef unsigned int u32;

__device__ __forceinline__ u32 f2h2(float hi, float lo) {
    u32 h;
    asm("cvt.rn.f16x2.f32 %0, %1, %2;" : "=r"(h) : "f"(hi), "f"(lo));
    return h;
}
__device__ __forceinline__ u32 hfma2(u32 a, u32 b, u32 c) {
    u32 d;
    asm("fma.rn.f16x2 %0, %1, %2, %3;" : "=r"(d) : "r"(a), "r"(b), "r"(c));
    return d;
}
__device__ __forceinline__ void hfma2i(u32& acc, u32 a, u32 b) {
    asm("fma.rn.f16x2 %0, %1, %2, %0;" : "+r"(acc) : "r"(a), "r"(b));
}
__device__ __forceinline__ u32 tanh2(u32 h) {
    u32 t;
    asm("tanh.approx.f16x2 %0, %1;" : "=r"(t) : "r"(h));
    return t;
}
__device__ __forceinline__ u32 hadd2(u32 a, u32 b) {
    u32 d;
    asm("add.rn.f16x2 %0, %1, %2;" : "=r"(d) : "r"(a), "r"(b));
    return d;
}

__global__ __launch_bounds__(128, 4)
void census_kernel(const float* __restrict__ x, const float* __restrict__ w,
                   const float* __restrict__ bias, const float* __restrict__ temp,
                   float* __restrict__ out) {
    __shared__ u32 smh[NROWS * SROW];   // dup'd half2 tile: (v,v) per input value
    __shared__ u32 wsm[9][4];           // [tap k][pair p] = h2(w_2p, w_2p+1), scaled
    __shared__ u32 bsm[4];              // bias pairs, scaled

    const int bid   = blockIdx.x;
    const int strip = bid & 7;          // H_/R_ = 8 strips
    const int c     = (bid >> 3) & 63;
    const int b     = bid >> 9;
    const int h0    = strip * R_;
    const int tid   = threadIdx.x;

    const float* xp = x + ((size_t)(b * C_ + c) * H_) * W_;

    // ---- weight prep: w layout HWIO flattened w[(kh*3+kw)*512 + c*8 + m]
    if (tid < 40) {
        const float sc = 0.5f * __ldg(&temp[c]);
        if (tid < 36) {
            const int k = tid >> 2, p = tid & 3;
            const float w0 = __ldg(&w[k * 512 + (c << 3) + 2 * p])     * sc;
            const float w1 = __ldg(&w[k * 512 + (c << 3) + 2 * p + 1]) * sc;
            wsm[k][p] = f2h2(w1, w0);
        } else {
            const int p = tid - 36;
            const float b0 = __ldg(&bias[(c << 3) + 2 * p])     * sc;
            const float b1 = __ldg(&bias[(c << 3) + 2 * p + 1]) * sc;
            bsm[p] = f2h2(b1, b0);
        }
    }

    // ---- tile load: smh[r][col+1] = h2dup(x[h0+r-1][col]); idx 0 and 257 are
    // the zero conv padding (tiles span the full width).
    #pragma unroll
    for (int i = tid; i < NROWS * 64; i += 128) {
        const int r  = i >> 6;
        const int c4 = (i & 63) << 2;
        const int gh = h0 + r - 1;
        float4 v = make_float4(0.f, 0.f, 0.f, 0.f);
        if (gh >= 0 && gh < H_) v = *(const float4*)(xp + gh * W_ + c4);
        u32* dst = &smh[r * SROW + c4 + 1];
        dst[0] = f2h2(v.x, v.x);
        dst[1] = f2h2(v.y, v.y);
        dst[2] = f2h2(v.z, v.z);
        dst[3] = f2h2(v.w, v.w);
    }
    if (tid < NROWS) {
        smh[tid * SROW + 0]   = 0u;
        smh[tid * SROW + 257] = 0u;
    }
    __syncthreads();

    const u32 bp0 = bsm[0], bp1 = bsm[1], bp2 = bsm[2], bp3 = bsm[3];

    const int tx = tid & 63;   // 64 threads across width, 4 cols each
    const int ty = tid >> 6;   // 2 row-groups
    float* outp = out + (((size_t)(b * C_ + c) * H_) + h0) * W_ + (tx << 2);

    // conv of one output row into acc[p][j] (p = multiplier pair, j = column).
    // window cols 4tx-1..4tx+4 = smh idx 4tx..4tx+5: LDS.128 + LDS.64, aligned.
    auto conv = [&](int r, u32 acc[4][4]) {
        #pragma unroll
        for (int kh = 0; kh < 3; kh++) {
            const u32* rp = &smh[(r + kh) * SROW + (tx << 2)];
            const uint4 dA = *(const uint4*)rp;         // d0..d3
            const uint2 dB = *(const uint2*)(rp + 4);   // d4,d5
            const u32 d[6] = {dA.x, dA.y, dA.z, dA.w, dB.x, dB.y};
            if (kh == 0) {
                // kw=0 with bias folded into the addend
                const uint4 wv = *(const uint4*)&wsm[0][0];
                #pragma unroll
                for (int j = 0; j < 4; j++) {
                    acc[0][j] = hfma2(d[j], wv.x, bp0);
                    acc[1][j] = hfma2(d[j], wv.y, bp1);
                    acc[2][j] = hfma2(d[j], wv.z, bp2);
                    acc[3][j] = hfma2(d[j], wv.w, bp3);
                }
                #pragma unroll
                for (int kw = 1; kw < 3; kw++) {
                    const uint4 wk = *(const uint4*)&wsm[kw][0];
                    #pragma unroll
                    for (int j = 0; j < 4; j++) {
                        hfma2i(acc[0][j], d[j + kw], wk.x);
                        hfma2i(acc[1][j], d[j + kw], wk.y);
                        hfma2i(acc[2][j], d[j + kw], wk.z);
                        hfma2i(acc[3][j], d[j + kw], wk.w);
                    }
                }
            } else {
                #pragma unroll
                for (int kw = 0; kw < 3; kw++) {
                    const uint4 wk = *(const uint4*)&wsm[kh * 3 + kw][0];
                    #pragma unroll
                    for (int j = 0; j < 4; j++) {
                        hfma2i(acc[0][j], d[j + kw], wk.x);
                        hfma2i(acc[1][j], d[j + kw], wk.y);
                        hfma2i(acc[2][j], d[j + kw], wk.z);
                        hfma2i(acc[3][j], d[j + kw], wk.w);
                    }
                }
            }
        }
    };

    // epilogue: per column, 4 f16x2 tanh -> hadd2 tree -> mean in f32
    auto epi = [&](u32 acc[4][4], int r) {
        float4 o;
        float* of = &o.x;
        #pragma unroll
        for (int j = 0; j < 4; j++) {
            const u32 t01 = hadd2(tanh2(acc[0][j]), tanh2(acc[1][j]));
            const u32 t23 = hadd2(tanh2(acc[2][j]), tanh2(acc[3][j]));
            const u32 v   = hadd2(t01, t23);
            __half2 hv;
            memcpy(&hv, &v, 4);
            const float2 vf = __half22float2(hv);
            of[j] = fmaf(vf.x + vf.y, 0.0625f, 0.5f);
        }
        *(float4*)(outp + r * W_) = o;
    };

    // software pipeline: epi(row k) overlaps conv(row k+1)
    u32 accA[4][4], accB[4][4];
    int r = ty;
    conv(r, accA);
    #pragma unroll 1
    for (int i = 0; i < 7; i++) {
        conv(r + 2, accB);
        epi(accA, r);
        conv(r + 4, accA);
        epi(accB, r + 2);
        r += 4;
    }
    conv(r + 2, accB);
    epi(accA, r);
    epi(accB, r + 2);
}

extern "C" void kernel_launch(void* const* d_in, const int* in_sizes, int n_in,
                              void* d_out, int out_size) {
    const float* x    = (const float*)d_in[0];
    const float* w    = (const float*)d_in[1];
    const float* bias = (const float*)d_in[2];
    const float* temp = (const float*)d_in[3];
    float* out = (float*)d_out;

    const int grid = B_ * C_ * (H_ / R_);   // 4*64*8 = 2048 blocks
    census_kernel<<<grid, 128>>>(x, w, bias, temp, out);
}